// round 9
// baseline (speedup 1.0000x reference)
#include <cuda_runtime.h>
#include <math.h>
#include <stdint.h>

#define NG    2048
#define NPG   24
#define EPG   288
#define KGB   32
#define EMB   32
#define DH    64
#define NT    256
#define NPAIR (NPG*NPG)          // 576
#define NATOM 10
#define PEPAD 36                 // Pe row pitch in words (bank-conflict-free A frags)
#define WTPAD 72                 // Wt row pitch in words (bank-conflict-free B frags)
#define MTILES (EPG/16)          // 18

typedef unsigned long long ull;

// ---------------- packed fp32x2 helpers ----------------
__device__ __forceinline__ ull pk2(float lo, float hi) {
    ull r; asm("mov.b64 %0, {%1, %2};" : "=l"(r) : "f"(lo), "f"(hi)); return r;
}
__device__ __forceinline__ void upk2(ull v, float& lo, float& hi) {
    asm("mov.b64 {%0, %1}, %2;" : "=f"(lo), "=f"(hi) : "l"(v));
}
__device__ __forceinline__ ull ffma2(ull a, ull b, ull c) {
    ull d; asm("fma.rn.f32x2 %0, %1, %2, %3;" : "=l"(d) : "l"(a), "l"(b), "l"(c)); return d;
}
__device__ __forceinline__ float fex2(float x) {
    float r; asm("ex2.approx.f32 %0, %1;" : "=f"(r) : "f"(x)); return r;
}
__device__ __forceinline__ uint32_t tf32r(float x) {
    uint32_t r; asm("cvt.rna.tf32.f32 %0, %1;" : "=r"(r) : "f"(x)); return r;
}
// m16n8k8 tf32 MMA (Ampere-class, legal on compute_103)
__device__ __forceinline__ void mma_tf32(float* c, const uint32_t* a,
                                         uint32_t b0, uint32_t b1) {
    asm volatile("mma.sync.aligned.m16n8k8.row.col.f32.tf32.tf32.f32 "
        "{%0,%1,%2,%3}, {%4,%5,%6,%7}, {%8,%9}, {%0,%1,%2,%3};"
        : "+f"(c[0]), "+f"(c[1]), "+f"(c[2]), "+f"(c[3])
        : "r"(a[0]), "r"(a[1]), "r"(a[2]), "r"(a[3]), "r"(b0), "r"(b1));
}

// ---------------- shared memory layout (4-byte words) ----------------
#define OFF_PE    0                          // 288*36 = 10368 (tf32)
#define OFF_WT    (OFF_PE + EPG*PEPAD)       // 32*72 = 2304 (tf32, We as [k][n])
#define OFF_XV    (OFF_WT + KGB*WTPAD)       // 576
#define OFF_S     (OFF_XV + NPAIR)           // 768
#define OFF_GNF   (OFF_S + NPG*KGB)          // 768
#define OFF_WEP   (OFF_GNF + NPG*EMB)        // 1024 (ull packed [kk][m])
#define OFF_MUL   (OFF_WEP + KGB*EMB)        // 100
#define OFF_BIAS  (OFF_MUL + NATOM*NATOM)    // 100
#define OFF_C1    (OFF_BIAS + NATOM*NATOM)   // 32
#define OFF_C2    (OFF_C1 + KGB)             // 32
#define OFF_NORM  (OFF_C2 + KGB)             // 32
#define OFF_BEP   (OFF_NORM + KGB)           // 32
#define OFF_BN    (OFF_BEP + EMB)            // 64
#define OFF_BE    (OFF_BN + DH)              // 64
#define OFF_AE    (OFF_BE + DH)              // 320
#define OFF_POS   (OFF_AE + NATOM*EMB)       // 72
#define OFF_EPAIR (OFF_POS + NPG*3)          // 288
#define OFF_Z     (OFF_EPAIR + EPG)          // 24
#define SMEM_WORDS (OFF_Z + NPG)             // 16968 words = 67872 B
#define SMEM_BYTES (SMEM_WORDS * 4)

extern __shared__ float sm[];

__global__ __launch_bounds__(NT, 3)
void gps_graph_kernel(const int* __restrict__ z,
                      const float* __restrict__ pos,
                      const int* __restrict__ edge_index,
                      const float* __restrict__ atom_emb,
                      const float* __restrict__ Wep,
                      const float* __restrict__ bep,
                      const float* __restrict__ means,
                      const float* __restrict__ stds,
                      const float* __restrict__ gmul,
                      const float* __restrict__ gbias,
                      const float* __restrict__ Wn,
                      const float* __restrict__ bn,
                      const float* __restrict__ We,
                      const float* __restrict__ be,
                      float* __restrict__ out_nodes,
                      float* __restrict__ out_edges,
                      int E)
{
    const int g    = blockIdx.x;
    const int tid  = threadIdx.x;
    const int wid  = tid >> 5;
    const int lane = tid & 31;
    const int zbase = g * NPG;
    const int ebase = g * EPG;

    uint32_t* PeU  = (uint32_t*)(sm + OFF_PE);
    uint32_t* WtU  = (uint32_t*)(sm + OFF_WT);
    float* Xv    = sm + OFF_XV;
    float* Ssum  = sm + OFF_S;
    float* Gnf   = sm + OFF_GNF;
    ull*   sWep2 = (ull*)(sm + OFF_WEP);
    float* sMul  = sm + OFF_MUL;
    float* sBias = sm + OFF_BIAS;
    float* sC1   = sm + OFF_C1;
    float* sC2   = sm + OFF_C2;
    float* sNorm = sm + OFF_NORM;
    float* sBep  = sm + OFF_BEP;
    float* sBn   = sm + OFF_BN;
    float* sBe   = sm + OFF_BE;
    float* sAe   = sm + OFF_AE;
    float* sPos  = sm + OFF_POS;
    int*   sEPair= (int*)(sm + OFF_EPAIR);
    int*   sZ    = (int*)(sm + OFF_Z);

    // ---- phase 0: tables ----
    if (tid < NPG) sZ[tid] = z[zbase + tid];
    for (int t = tid; t < NPG*3; t += NT) sPos[t] = pos[zbase*3 + t];
    for (int t = tid; t < (KGB/2)*EMB; t += NT) {
        int kk = t >> 5, m = t & 31;
        sWep2[kk * EMB + m] = pk2(Wep[(2*kk)*EMB + m], Wep[(2*kk+1)*EMB + m]);
    }
    for (int t = tid; t < NATOM*NATOM; t += NT) { sMul[t] = gmul[t]; sBias[t] = gbias[t]; }
    if (tid < KGB) {
        float s = fabsf(stds[tid]) + 1e-5f;
        float ik = 1.0f / s;
        float c1 = 0.8493218002880191f * ik;        // sqrt(0.5*log2(e))/s
        sC1[tid] = c1;
        sC2[tid] = -means[tid] * c1;
        sNorm[tid] = 0.3989422804014327f * ik;      // 1/(sqrt(2pi)*s)
    }
    if (tid >= KGB && tid < 2*KGB) sBep[tid - KGB] = bep[tid - KGB];
    if (tid >= 64 && tid < 128)  sBn[tid - 64] = bn[tid - 64];
    if (tid >= 128 && tid < 192) sBe[tid - 128] = be[tid - 128];
    for (int t = tid; t < NATOM*EMB; t += NT) sAe[t] = atom_emb[t];
    // Wt[k][n] = tf32(We[k][n]) with pad-72 rows
    for (int t = tid; t < KGB*DH; t += NT) {
        int k = t >> 6, n = t & 63;
        WtU[k * WTPAD + n] = tf32r(We[t]);
    }
    __syncthreads();

    // ---- phase 1: Xv (pair affine args), edge pair indices ----
    for (int p = tid; p < NPAIR; p += NT) {
        int i = p / NPG;
        int j = p - i * NPG;
        float dx = sPos[i*3+0] - sPos[j*3+0];
        float dy = sPos[i*3+1] - sPos[j*3+1];
        float dz = sPos[i*3+2] - sPos[j*3+2];
        float sq = dx*dx + dy*dy + dz*dz;
        float dist = (sq == 0.0f) ? 0.0f : sqrtf(sq);
        int et = sZ[i] * NATOM + sZ[j];
        Xv[p] = sMul[et] * dist + sBias[et];
    }
    for (int e = tid; e < EPG; e += NT) {
        int src = edge_index[ebase + e];
        int dst = edge_index[E + ebase + e];
        sEPair[e] = (dst - zbase) * NPG + (src - zbase);
    }
    __syncthreads();

    // ---- phase 2: Pe rows (tf32, pad 36) + node sums ----
    {
        const int k = lane;
        const float c1k = sC1[k], c2k = sC2[k], nk = sNorm[k];
        // edge rows
        for (int t = tid; t < EPG * KGB; t += NT) {
            int e = t >> 5;
            float x = Xv[sEPair[e]];
            float b = fmaf(x, c1k, c2k);
            PeU[e * PEPAD + k] = tf32r(nk * fex2(-b * b));
        }
        // node sums S[i][k] = nk * sum_j exp2(-(c1*x+c2)^2)
        for (int t = tid; t < NPG * KGB; t += NT) {
            int i = t >> 5;
            const float* xr = Xv + i * NPG;
            float s0 = 0.0f, s1 = 0.0f;
            #pragma unroll
            for (int j = 0; j < NPG; j += 2) {
                float b0 = fmaf(xr[j],   c1k, c2k);
                float b1 = fmaf(xr[j+1], c1k, c2k);
                s0 += fex2(-b0 * b0);
                s1 += fex2(-b1 * b1);
            }
            Ssum[t] = nk * (s0 + s1);
        }
    }
    __syncthreads();

    // ---- phase 3: gnf = atom_emb[z_i] + S @ Wep + bep ----
    for (int t = tid; t < NPG * EMB; t += NT) {
        int i = t >> 5, m = t & 31;
        const ull* s2 = (const ull*)(Ssum + i * KGB);
        ull acc = 0;
        #pragma unroll
        for (int kk = 0; kk < KGB/2; ++kk)
            acc = ffma2(s2[kk], sWep2[kk * EMB + m], acc);
        float lo, hi; upk2(acc, lo, hi);
        Gnf[t] = sAe[sZ[i] * EMB + m] + sBep[m] + lo + hi;
    }
    __syncthreads();

    // ---- phase 4a: node_feat = gnf @ W_nodes + b_nodes ----
    {
        const int d = tid & (DH - 1);
        const int isub = tid >> 6;
        ull w[EMB/2];
        #pragma unroll
        for (int mm = 0; mm < EMB/2; ++mm)
            w[mm] = pk2(Wn[(2*mm)*DH + d], Wn[(2*mm+1)*DH + d]);
        const float bd = sBn[d];
        for (int i = isub; i < NPG; i += NT/DH) {
            const ull* g2 = (const ull*)(Gnf + i * EMB);
            ull a0 = 0, a1 = 0;
            #pragma unroll
            for (int mm = 0; mm < EMB/2; mm += 2) {
                a0 = ffma2(g2[mm],   w[mm],   a0);
                a1 = ffma2(g2[mm+1], w[mm+1], a1);
            }
            float l0, h0, l1, h1; upk2(a0, l0, h0); upk2(a1, l1, h1);
            out_nodes[(size_t)(zbase + i) * DH + d] = bd + l0 + h0 + l1 + h1;
        }
    }

    // ---- phase 4b: edge_feat = Pe @ We + be via m16n8k8 tf32 MMA ----
    // 18 M-tiles over 8 warps; per tile: 8 N-tiles x 4 K-steps
    {
        const int g4 = lane >> 2;      // group id 0..7
        const int t4 = lane & 3;       // thread-in-group 0..3
        for (int mt = wid; mt < MTILES; mt += 8) {
            const int m0 = mt * 16;
            const int r0 = (m0 + g4) * PEPAD;
            const int r1 = (m0 + g4 + 8) * PEPAD;
            uint32_t A[16];
            #pragma unroll
            for (int ks = 0; ks < 4; ++ks) {
                const int c0 = ks * 8 + t4;
                A[ks*4+0] = PeU[r0 + c0];
                A[ks*4+1] = PeU[r1 + c0];
                A[ks*4+2] = PeU[r0 + c0 + 4];
                A[ks*4+3] = PeU[r1 + c0 + 4];
            }
            float* orow0 = out_edges + (size_t)(ebase + m0 + g4) * DH;
            float* orow1 = out_edges + (size_t)(ebase + m0 + g4 + 8) * DH;
            #pragma unroll
            for (int nt = 0; nt < 8; ++nt) {
                float c[4] = {0.f, 0.f, 0.f, 0.f};
                #pragma unroll
                for (int ks = 0; ks < 4; ++ks) {
                    uint32_t b0 = WtU[(ks*8 + t4)     * WTPAD + nt*8 + g4];
                    uint32_t b1 = WtU[(ks*8 + t4 + 4) * WTPAD + nt*8 + g4];
                    mma_tf32(c, A + ks*4, b0, b1);
                }
                const int col = nt*8 + t4*2;
                const float bx = sBe[col], by = sBe[col+1];
                *(float2*)(orow0 + col) = make_float2(c[0] + bx, c[1] + by);
                *(float2*)(orow1 + col) = make_float2(c[2] + bx, c[3] + by);
            }
        }
    }
}

extern "C" void kernel_launch(void* const* d_in, const int* in_sizes, int n_in,
                              void* d_out, int out_size)
{
    const int*   z    = (const int*)  d_in[0];
    const float* pos  = (const float*)d_in[1];
    const int*   ei   = (const int*)  d_in[3];
    const float* ae   = (const float*)d_in[4];
    const float* Wep  = (const float*)d_in[5];
    const float* bep  = (const float*)d_in[6];
    const float* mea  = (const float*)d_in[7];
    const float* stds = (const float*)d_in[8];
    const float* gmul = (const float*)d_in[9];
    const float* gbia = (const float*)d_in[10];
    const float* Wn   = (const float*)d_in[11];
    const float* bn   = (const float*)d_in[12];
    const float* We   = (const float*)d_in[13];
    const float* be   = (const float*)d_in[14];

    const int N = in_sizes[0];          // 49152
    const int E = in_sizes[3] / 2;      // 589824
    const int g = N / NPG;              // 2048

    float* out_nodes = (float*)d_out;
    float* out_edges = out_nodes + (size_t)N * DH;

    cudaFuncSetAttribute(gps_graph_kernel,
                         cudaFuncAttributeMaxDynamicSharedMemorySize, SMEM_BYTES);

    gps_graph_kernel<<<g, NT, SMEM_BYTES>>>(
        z, pos, ei, ae, Wep, bep, mea, stds, gmul, gbia,
        Wn, bn, We, be, out_nodes, out_edges, E);
}

// round 10
// speedup vs baseline: 1.4213x; 1.4213x over previous
#include <cuda_runtime.h>
#include <math.h>
#include <stdint.h>

#define NG    2048
#define NPG   24
#define EPG   288
#define KGB   32
#define EMB   32
#define DH    64
#define NT    256
#define NPAIR (NPG*NPG)          // 576
#define NATOM 10

typedef unsigned long long ull;

// global scratch: per-pair affine args (graph-major)
__device__ float XvG[NG * NPAIR];

// ---------------- packed fp32x2 helpers ----------------
__device__ __forceinline__ ull pk2(float lo, float hi) {
    ull r; asm("mov.b64 %0, {%1, %2};" : "=l"(r) : "f"(lo), "f"(hi)); return r;
}
__device__ __forceinline__ void upk2(ull v, float& lo, float& hi) {
    asm("mov.b64 {%0, %1}, %2;" : "=f"(lo), "=f"(hi) : "l"(v));
}
__device__ __forceinline__ ull ffma2(ull a, ull b, ull c) {
    ull d; asm("fma.rn.f32x2 %0, %1, %2, %3;" : "=l"(d) : "l"(a), "l"(b), "l"(c)); return d;
}
__device__ __forceinline__ float fex2(float x) {
    float r; asm("ex2.approx.f32 %0, %1;" : "=f"(r) : "f"(x)); return r;
}
__device__ __forceinline__ uint32_t tf32r(float x) {
    uint32_t r; asm("cvt.rna.tf32.f32 %0, %1;" : "=r"(r) : "f"(x)); return r;
}
__device__ __forceinline__ void mma_tf32(float* c, const uint32_t* a,
                                         uint32_t b0, uint32_t b1) {
    asm volatile("mma.sync.aligned.m16n8k8.row.col.f32.tf32.tf32.f32 "
        "{%0,%1,%2,%3}, {%4,%5,%6,%7}, {%8,%9}, {%0,%1,%2,%3};"
        : "+f"(c[0]), "+f"(c[1]), "+f"(c[2]), "+f"(c[3])
        : "r"(a[0]), "r"(a[1]), "r"(a[2]), "r"(a[3]), "r"(b0), "r"(b1));
}

// =====================================================================
// K1: node path (per-graph). smem layout (words)
// =====================================================================
#define N_XV    0                          // 576
#define N_S     (N_XV   + NPAIR)           // 768
#define N_GNF   (N_S    + NPG*KGB)         // 768
#define N_WEP   (N_GNF  + NPG*EMB)         // 1024 (ull packed [kk][m])
#define N_MUL   (N_WEP  + KGB*EMB)         // 100
#define N_BIAS  (N_MUL  + NATOM*NATOM)     // 100
#define N_C1    (N_BIAS + NATOM*NATOM)     // 32
#define N_C2    (N_C1   + KGB)             // 32
#define N_NORM  (N_C2   + KGB)             // 32
#define N_BEP   (N_NORM + KGB)             // 32
#define N_BN    (N_BEP  + EMB)             // 64
#define N_AE    (N_BN   + DH)              // 320
#define N_POS   (N_AE   + NATOM*EMB)       // 72
#define N_Z     (N_POS  + NPG*3)           // 24
#define K1_WORDS (N_Z + NPG)
#define K1_BYTES (K1_WORDS * 4)

extern __shared__ float sm[];

__global__ __launch_bounds__(NT, 4)
void node_kernel(const int* __restrict__ z,
                 const float* __restrict__ pos,
                 const float* __restrict__ atom_emb,
                 const float* __restrict__ Wep,
                 const float* __restrict__ bep,
                 const float* __restrict__ means,
                 const float* __restrict__ stds,
                 const float* __restrict__ gmul,
                 const float* __restrict__ gbias,
                 const float* __restrict__ Wn,
                 const float* __restrict__ bn,
                 float* __restrict__ out_nodes)
{
    const int g   = blockIdx.x;
    const int tid = threadIdx.x;
    const int zbase = g * NPG;

    float* Xv    = sm + N_XV;
    float* Ssum  = sm + N_S;
    float* Gnf   = sm + N_GNF;
    ull*   sWep2 = (ull*)(sm + N_WEP);
    float* sMul  = sm + N_MUL;
    float* sBias = sm + N_BIAS;
    float* sC1   = sm + N_C1;
    float* sC2   = sm + N_C2;
    float* sNorm = sm + N_NORM;
    float* sBep  = sm + N_BEP;
    float* sBn   = sm + N_BN;
    float* sAe   = sm + N_AE;
    float* sPos  = sm + N_POS;
    int*   sZ    = (int*)(sm + N_Z);

    // ---- tables ----
    if (tid < NPG) sZ[tid] = z[zbase + tid];
    for (int t = tid; t < NPG*3; t += NT) sPos[t] = pos[zbase*3 + t];
    for (int t = tid; t < (KGB/2)*EMB; t += NT) {
        int kk = t >> 5, m = t & 31;
        sWep2[kk * EMB + m] = pk2(Wep[(2*kk)*EMB + m], Wep[(2*kk+1)*EMB + m]);
    }
    for (int t = tid; t < NATOM*NATOM; t += NT) { sMul[t] = gmul[t]; sBias[t] = gbias[t]; }
    if (tid < KGB) {
        float s = fabsf(stds[tid]) + 1e-5f;
        float ik = 1.0f / s;
        float c1 = 0.8493218002880191f * ik;        // sqrt(0.5*log2(e))/s
        sC1[tid] = c1;
        sC2[tid] = -means[tid] * c1;
        sNorm[tid] = 0.3989422804014327f * ik;
    }
    if (tid >= KGB && tid < 2*KGB) sBep[tid - KGB] = bep[tid - KGB];
    if (tid >= 64 && tid < 128)  sBn[tid - 64] = bn[tid - 64];
    for (int t = tid; t < NATOM*EMB; t += NT) sAe[t] = atom_emb[t];
    __syncthreads();

    // ---- Xv: per-pair affine args, also stored to global scratch ----
    float* xvg = XvG + g * NPAIR;
    for (int p = tid; p < NPAIR; p += NT) {
        int i = p / NPG;
        int j = p - i * NPG;
        float dx = sPos[i*3+0] - sPos[j*3+0];
        float dy = sPos[i*3+1] - sPos[j*3+1];
        float dz = sPos[i*3+2] - sPos[j*3+2];
        float sq = dx*dx + dy*dy + dz*dz;
        float dist = (sq == 0.0f) ? 0.0f : sqrtf(sq);
        int et = sZ[i] * NATOM + sZ[j];
        float x = sMul[et] * dist + sBias[et];
        Xv[p] = x;
        xvg[p] = x;
    }
    __syncthreads();

    // ---- node sums S[i][k] = nk * sum_j exp2(-(c1*x+c2)^2) ----
    {
        const int k = tid & 31;
        const float c1k = sC1[k], c2k = sC2[k], nk = sNorm[k];
        for (int t = tid; t < NPG * KGB; t += NT) {
            int i = t >> 5;
            const float* xr = Xv + i * NPG;
            float s0 = 0.0f, s1 = 0.0f;
            #pragma unroll
            for (int j = 0; j < NPG; j += 2) {
                float b0 = fmaf(xr[j],   c1k, c2k);
                float b1 = fmaf(xr[j+1], c1k, c2k);
                s0 += fex2(-b0 * b0);
                s1 += fex2(-b1 * b1);
            }
            Ssum[t] = nk * (s0 + s1);
        }
    }
    __syncthreads();

    // ---- gnf = atom_emb[z_i] + S @ Wep + bep ----
    for (int t = tid; t < NPG * EMB; t += NT) {
        int i = t >> 5, m = t & 31;
        const ull* s2 = (const ull*)(Ssum + i * KGB);
        ull acc = 0;
        #pragma unroll
        for (int kk = 0; kk < KGB/2; ++kk)
            acc = ffma2(s2[kk], sWep2[kk * EMB + m], acc);
        float lo, hi; upk2(acc, lo, hi);
        Gnf[t] = sAe[sZ[i] * EMB + m] + sBep[m] + lo + hi;
    }
    __syncthreads();

    // ---- node_feat = gnf @ W_nodes + b_nodes ----
    {
        const int d = tid & (DH - 1);
        const int isub = tid >> 6;
        ull w[EMB/2];
        #pragma unroll
        for (int mm = 0; mm < EMB/2; ++mm)
            w[mm] = pk2(Wn[(2*mm)*DH + d], Wn[(2*mm+1)*DH + d]);
        const float bd = sBn[d];
        for (int i = isub; i < NPG; i += NT/DH) {
            const ull* g2 = (const ull*)(Gnf + i * EMB);
            ull a0 = 0, a1 = 0;
            #pragma unroll
            for (int mm = 0; mm < EMB/2; mm += 2) {
                a0 = ffma2(g2[mm],   w[mm],   a0);
                a1 = ffma2(g2[mm+1], w[mm+1], a1);
            }
            float l0, h0, l1, h1; upk2(a0, l0, h0); upk2(a1, l1, h1);
            out_nodes[(size_t)(zbase + i) * DH + d] = bd + l0 + h0 + l1 + h1;
        }
    }
}

// =====================================================================
// K2: edge path. 128 edges per CTA, tf32 MMA, coalesced staged epilogue
// =====================================================================
#define EPC    128                         // edges per CTA
#define PEPAD  36
#define WTPAD  72
#define STPAD  72

#define E_PE    0                          // 128*36 = 4608
#define E_WT    (E_PE + EPC*PEPAD)         // 32*72 = 2304
#define E_STG   (E_WT + KGB*WTPAD)         // 8 warps * 16*72 = 9216
#define E_C1    (E_STG + 8*16*STPAD)       // 32
#define E_C2    (E_C1 + KGB)               // 32
#define E_NORM  (E_C2 + KGB)               // 32
#define E_BE    (E_NORM + KGB)             // 64
#define K2_WORDS (E_BE + DH)               // 16288 words = 65152 B
#define K2_BYTES (K2_WORDS * 4)

__global__ __launch_bounds__(NT, 3)
void edge_kernel(const int* __restrict__ edge_index,
                 const float* __restrict__ We,
                 const float* __restrict__ be,
                 const float* __restrict__ means,
                 const float* __restrict__ stds,
                 float* __restrict__ out_edges,
                 int E)
{
    const int tid  = threadIdx.x;
    const int wid  = tid >> 5;
    const int lane = tid & 31;
    const int e0   = blockIdx.x * EPC;

    uint32_t* PeU = (uint32_t*)(sm + E_PE);
    uint32_t* WtU = (uint32_t*)(sm + E_WT);
    float*    Stg = sm + E_STG;
    float*    sC1 = sm + E_C1;
    float*    sC2 = sm + E_C2;
    float*    sNm = sm + E_NORM;
    float*    sBe = sm + E_BE;

    // consts
    if (tid < KGB) {
        float s = fabsf(stds[tid]) + 1e-5f;
        float ik = 1.0f / s;
        float c1 = 0.8493218002880191f * ik;
        sC1[tid] = c1;
        sC2[tid] = -means[tid] * c1;
        sNm[tid] = 0.3989422804014327f * ik;
    }
    if (tid >= 32 && tid < 96) sBe[tid - 32] = be[tid - 32];
    // Wt[k][n] = tf32(We[k][n]), pitch 72
    for (int t = tid; t < KGB*DH; t += NT) {
        int k = t >> 6, n = t & 63;
        WtU[k * WTPAD + n] = tf32r(We[t]);
    }
    __syncthreads();

    // Pe: 2 threads per edge, 16 gaussians each
    {
        const int el = tid >> 1;
        const int kh = (tid & 1) * 16;
        const int eg = e0 + el;
        int src = edge_index[eg];
        int dst = edge_index[E + eg];
        int gg  = eg / EPG;
        int zb  = gg * NPG;
        float x = XvG[gg * NPAIR + (dst - zb) * NPG + (src - zb)];
        #pragma unroll
        for (int q = 0; q < 16; ++q) {
            int k = kh + q;
            float b = fmaf(x, sC1[k], sC2[k]);
            PeU[el * PEPAD + k] = tf32r(sNm[k] * fex2(-b * b));
        }
    }
    __syncthreads();

    // MMA: warp wid handles edges [wid*16, wid*16+16)
    {
        const int g4 = lane >> 2;
        const int t4 = lane & 3;
        const int m0 = wid * 16;
        const int r0 = (m0 + g4) * PEPAD;
        const int r1 = (m0 + g4 + 8) * PEPAD;
        uint32_t A[16];
        #pragma unroll
        for (int ks = 0; ks < 4; ++ks) {
            const int c0 = ks * 8 + t4;
            A[ks*4+0] = PeU[r0 + c0];
            A[ks*4+1] = PeU[r1 + c0];
            A[ks*4+2] = PeU[r0 + c0 + 4];
            A[ks*4+3] = PeU[r1 + c0 + 4];
        }
        float* stg = Stg + wid * 16 * STPAD;
        #pragma unroll
        for (int nt = 0; nt < 8; ++nt) {
            float c[4] = {0.f, 0.f, 0.f, 0.f};
            #pragma unroll
            for (int ks = 0; ks < 4; ++ks) {
                uint32_t b0 = WtU[(ks*8 + t4)     * WTPAD + nt*8 + g4];
                uint32_t b1 = WtU[(ks*8 + t4 + 4) * WTPAD + nt*8 + g4];
                mma_tf32(c, A + ks*4, b0, b1);
            }
            *(float2*)(stg + g4       * STPAD + nt*8 + t4*2) = make_float2(c[0], c[1]);
            *(float2*)(stg + (g4 + 8) * STPAD + nt*8 + t4*2) = make_float2(c[2], c[3]);
        }
        __syncwarp();

        // coalesced writeout with bias: thread lane -> rows (lane>>3)+4p, cols (lane&7)*4+32h
        const int colb = (lane & 7) * 4;
        const int rowb = lane >> 3;
        float4 b0 = *(const float4*)(sBe + colb);
        float4 b1 = *(const float4*)(sBe + colb + 32);
        #pragma unroll
        for (int p = 0; p < 4; ++p) {
            const int r = rowb + 4*p;
            float4 v0 = *(const float4*)(stg + r * STPAD + colb);
            float4 v1 = *(const float4*)(stg + r * STPAD + colb + 32);
            v0.x += b0.x; v0.y += b0.y; v0.z += b0.z; v0.w += b0.w;
            v1.x += b1.x; v1.y += b1.y; v1.z += b1.z; v1.w += b1.w;
            float* o = out_edges + (size_t)(e0 + m0 + r) * DH;
            *(float4*)(o + colb)      = v0;
            *(float4*)(o + colb + 32) = v1;
        }
    }
}

extern "C" void kernel_launch(void* const* d_in, const int* in_sizes, int n_in,
                              void* d_out, int out_size)
{
    const int*   z    = (const int*)  d_in[0];
    const float* pos  = (const float*)d_in[1];
    const int*   ei   = (const int*)  d_in[3];
    const float* ae   = (const float*)d_in[4];
    const float* Wep  = (const float*)d_in[5];
    const float* bep  = (const float*)d_in[6];
    const float* mea  = (const float*)d_in[7];
    const float* stds = (const float*)d_in[8];
    const float* gmul = (const float*)d_in[9];
    const float* gbia = (const float*)d_in[10];
    const float* Wn   = (const float*)d_in[11];
    const float* bn   = (const float*)d_in[12];
    const float* We   = (const float*)d_in[13];
    const float* be   = (const float*)d_in[14];

    const int N = in_sizes[0];          // 49152
    const int E = in_sizes[3] / 2;      // 589824
    const int g = N / NPG;              // 2048

    float* out_nodes = (float*)d_out;
    float* out_edges = out_nodes + (size_t)N * DH;

    cudaFuncSetAttribute(node_kernel,
                         cudaFuncAttributeMaxDynamicSharedMemorySize, K1_BYTES);
    cudaFuncSetAttribute(edge_kernel,
                         cudaFuncAttributeMaxDynamicSharedMemorySize, K2_BYTES);

    node_kernel<<<g, NT, K1_BYTES>>>(z, pos, ae, Wep, bep, mea, stds,
                                     gmul, gbia, Wn, bn, out_nodes);
    edge_kernel<<<E / EPC, NT, K2_BYTES>>>(ei, We, be, mea, stds, out_edges, E);
}

// round 11
// speedup vs baseline: 1.7060x; 1.2003x over previous
#include <cuda_runtime.h>
#include <math.h>
#include <stdint.h>

#define NG    2048
#define NPG   24
#define EPG   288
#define KGB   32
#define EMB   32
#define DH    64
#define NT    256
#define NPAIR (NPG*NPG)          // 576
#define NATOM 10

typedef unsigned long long ull;

// global scratch: per-pair affine args (graph-major)
__device__ float XvG[NG * NPAIR];

// ---------------- packed fp32x2 helpers ----------------
__device__ __forceinline__ ull pk2(float lo, float hi) {
    ull r; asm("mov.b64 %0, {%1, %2};" : "=l"(r) : "f"(lo), "f"(hi)); return r;
}
__device__ __forceinline__ void upk2(ull v, float& lo, float& hi) {
    asm("mov.b64 {%0, %1}, %2;" : "=f"(lo), "=f"(hi) : "l"(v));
}
__device__ __forceinline__ ull ffma2(ull a, ull b, ull c) {
    ull d; asm("fma.rn.f32x2 %0, %1, %2, %3;" : "=l"(d) : "l"(a), "l"(b), "l"(c)); return d;
}
__device__ __forceinline__ float fex2(float x) {
    float r; asm("ex2.approx.f32 %0, %1;" : "=f"(r) : "f"(x)); return r;
}
__device__ __forceinline__ uint32_t tf32r(float x) {
    uint32_t r; asm("cvt.rna.tf32.f32 %0, %1;" : "=r"(r) : "f"(x)); return r;
}
__device__ __forceinline__ void mma_tf32(float* c, const uint32_t* a,
                                         uint32_t b0, uint32_t b1) {
    asm volatile("mma.sync.aligned.m16n8k8.row.col.f32.tf32.tf32.f32 "
        "{%0,%1,%2,%3}, {%4,%5,%6,%7}, {%8,%9}, {%0,%1,%2,%3};"
        : "+f"(c[0]), "+f"(c[1]), "+f"(c[2]), "+f"(c[3])
        : "r"(a[0]), "r"(a[1]), "r"(a[2]), "r"(a[3]), "r"(b0), "r"(b1));
}

// =====================================================================
// K1: node path (per-graph). smem layout (words)
// =====================================================================
#define N_XV    0                          // 576
#define N_S     (N_XV   + NPAIR)           // 768
#define N_GNF   (N_S    + NPG*KGB)         // 768
#define N_WEP   (N_GNF  + NPG*EMB)         // 1024 (ull packed [kk][m])
#define N_MUL   (N_WEP  + KGB*EMB)         // 100
#define N_BIAS  (N_MUL  + NATOM*NATOM)     // 100
#define N_C1    (N_BIAS + NATOM*NATOM)     // 32
#define N_C2    (N_C1   + KGB)             // 32
#define N_NORM  (N_C2   + KGB)             // 32
#define N_BEP   (N_NORM + KGB)             // 32
#define N_BN    (N_BEP  + EMB)             // 64
#define N_AE    (N_BN   + DH)              // 320
#define N_POS   (N_AE   + NATOM*EMB)       // 72
#define N_Z     (N_POS  + NPG*3)           // 24
#define K1_WORDS (N_Z + NPG)
#define K1_BYTES (K1_WORDS * 4)

extern __shared__ float sm[];

__global__ __launch_bounds__(NT, 4)
void node_kernel(const int* __restrict__ z,
                 const float* __restrict__ pos,
                 const float* __restrict__ atom_emb,
                 const float* __restrict__ Wep,
                 const float* __restrict__ bep,
                 const float* __restrict__ means,
                 const float* __restrict__ stds,
                 const float* __restrict__ gmul,
                 const float* __restrict__ gbias,
                 const float* __restrict__ Wn,
                 const float* __restrict__ bn,
                 float* __restrict__ out_nodes)
{
    const int g   = blockIdx.x;
    const int tid = threadIdx.x;
    const int zbase = g * NPG;

    float* Xv    = sm + N_XV;
    float* Ssum  = sm + N_S;
    float* Gnf   = sm + N_GNF;
    ull*   sWep2 = (ull*)(sm + N_WEP);
    float* sMul  = sm + N_MUL;
    float* sBias = sm + N_BIAS;
    float* sC1   = sm + N_C1;
    float* sC2   = sm + N_C2;
    float* sNorm = sm + N_NORM;
    float* sBep  = sm + N_BEP;
    float* sBn   = sm + N_BN;
    float* sAe   = sm + N_AE;
    float* sPos  = sm + N_POS;
    int*   sZ    = (int*)(sm + N_Z);

    // ---- tables ----
    if (tid < NPG) sZ[tid] = z[zbase + tid];
    for (int t = tid; t < NPG*3; t += NT) sPos[t] = pos[zbase*3 + t];
    for (int t = tid; t < (KGB/2)*EMB; t += NT) {
        int kk = t >> 5, m = t & 31;
        sWep2[kk * EMB + m] = pk2(Wep[(2*kk)*EMB + m], Wep[(2*kk+1)*EMB + m]);
    }
    for (int t = tid; t < NATOM*NATOM; t += NT) { sMul[t] = gmul[t]; sBias[t] = gbias[t]; }
    if (tid < KGB) {
        float s = fabsf(stds[tid]) + 1e-5f;
        float ik = 1.0f / s;
        float c1 = 0.8493218002880191f * ik;        // sqrt(0.5*log2(e))/s
        sC1[tid] = c1;
        sC2[tid] = -means[tid] * c1;
        sNorm[tid] = 0.3989422804014327f * ik;
    }
    if (tid >= KGB && tid < 2*KGB) sBep[tid - KGB] = bep[tid - KGB];
    if (tid >= 64 && tid < 128)  sBn[tid - 64] = bn[tid - 64];
    for (int t = tid; t < NATOM*EMB; t += NT) sAe[t] = atom_emb[t];
    __syncthreads();

    // ---- Xv: per-pair affine args, also stored to global scratch ----
    float* xvg = XvG + g * NPAIR;
    for (int p = tid; p < NPAIR; p += NT) {
        int i = p / NPG;
        int j = p - i * NPG;
        float dx = sPos[i*3+0] - sPos[j*3+0];
        float dy = sPos[i*3+1] - sPos[j*3+1];
        float dz = sPos[i*3+2] - sPos[j*3+2];
        float sq = dx*dx + dy*dy + dz*dz;
        float dist = (sq == 0.0f) ? 0.0f : sqrtf(sq);
        int et = sZ[i] * NATOM + sZ[j];
        float x = sMul[et] * dist + sBias[et];
        Xv[p] = x;
        xvg[p] = x;
    }
    __syncthreads();

    // ---- node sums S[i][k] = nk * sum_j exp2(-(c1*x+c2)^2) ----
    {
        const int k = tid & 31;
        const float c1k = sC1[k], c2k = sC2[k], nk = sNorm[k];
        for (int t = tid; t < NPG * KGB; t += NT) {
            int i = t >> 5;
            const float* xr = Xv + i * NPG;
            float s0 = 0.0f, s1 = 0.0f;
            #pragma unroll
            for (int j = 0; j < NPG; j += 2) {
                float b0 = fmaf(xr[j],   c1k, c2k);
                float b1 = fmaf(xr[j+1], c1k, c2k);
                s0 += fex2(-b0 * b0);
                s1 += fex2(-b1 * b1);
            }
            Ssum[t] = nk * (s0 + s1);
        }
    }
    __syncthreads();

    // ---- gnf = atom_emb[z_i] + S @ Wep + bep ----
    for (int t = tid; t < NPG * EMB; t += NT) {
        int i = t >> 5, m = t & 31;
        const ull* s2 = (const ull*)(Ssum + i * KGB);
        ull acc = 0;
        #pragma unroll
        for (int kk = 0; kk < KGB/2; ++kk)
            acc = ffma2(s2[kk], sWep2[kk * EMB + m], acc);
        float lo, hi; upk2(acc, lo, hi);
        Gnf[t] = sAe[sZ[i] * EMB + m] + sBep[m] + lo + hi;
    }
    __syncthreads();

    // ---- node_feat = gnf @ W_nodes + b_nodes ----
    {
        const int d = tid & (DH - 1);
        const int isub = tid >> 6;
        ull w[EMB/2];
        #pragma unroll
        for (int mm = 0; mm < EMB/2; ++mm)
            w[mm] = pk2(Wn[(2*mm)*DH + d], Wn[(2*mm+1)*DH + d]);
        const float bd = sBn[d];
        for (int i = isub; i < NPG; i += NT/DH) {
            const ull* g2 = (const ull*)(Gnf + i * EMB);
            ull a0 = 0, a1 = 0;
            #pragma unroll
            for (int mm = 0; mm < EMB/2; mm += 2) {
                a0 = ffma2(g2[mm],   w[mm],   a0);
                a1 = ffma2(g2[mm+1], w[mm+1], a1);
            }
            float l0, h0, l1, h1; upk2(a0, l0, h0); upk2(a1, l1, h1);
            out_nodes[(size_t)(zbase + i) * DH + d] = bd + l0 + h0 + l1 + h1;
        }
    }
}

// =====================================================================
// K2: edge path. 128 edges/CTA, tf32 MMA, 2-pass epilogue overlaid on Pe
// smem = 28.3 KB -> 4+ CTAs/SM
// =====================================================================
#define EPC    128                         // edges per CTA
#define PEPAD  36                          // Pe pitch (16 rows/warp)
#define STPAD  72                          // staging pitch (8 rows/warp, same 576w block)
#define WTPAD  72

#define E_PE    0                          // 8 warps * 576 = 4608 words
#define E_WT    (E_PE + EPC*PEPAD)         // 2304
#define E_C1    (E_WT + KGB*WTPAD)         // 32
#define E_C2    (E_C1 + KGB)               // 32
#define E_NORM  (E_C2 + KGB)               // 32
#define E_BE    (E_NORM + KGB)             // 64
#define K2_WORDS (E_BE + DH)               // 7072 words = 28288 B
#define K2_BYTES (K2_WORDS * 4)

__global__ __launch_bounds__(NT, 4)
void edge_kernel(const int* __restrict__ edge_index,
                 const float* __restrict__ We,
                 const float* __restrict__ be,
                 const float* __restrict__ means,
                 const float* __restrict__ stds,
                 float* __restrict__ out_edges,
                 int E)
{
    const int tid  = threadIdx.x;
    const int wid  = tid >> 5;
    const int lane = tid & 31;
    const int e0   = blockIdx.x * EPC;

    uint32_t* PeU = (uint32_t*)(sm + E_PE);
    uint32_t* WtU = (uint32_t*)(sm + E_WT);
    float*    sC1 = sm + E_C1;
    float*    sC2 = sm + E_C2;
    float*    sNm = sm + E_NORM;
    float*    sBe = sm + E_BE;

    // ---- prefetch the edge gather chain FIRST (overlaps table setup) ----
    const int el = tid >> 1;           // edge-local 0..127
    const int kh = (tid & 1) * 16;     // gaussian half
    const int eg = e0 + el;
    int src = edge_index[eg];          // LDG issued early
    int dst = edge_index[E + eg];      // LDG issued early

    // ---- tables (overlap with gather latency) ----
    if (tid < KGB) {
        float s = fabsf(stds[tid]) + 1e-5f;
        float ik = 1.0f / s;
        float c1 = 0.8493218002880191f * ik;
        sC1[tid] = c1;
        sC2[tid] = -means[tid] * c1;
        sNm[tid] = 0.3989422804014327f * ik;
    }
    if (tid >= 32 && tid < 96) sBe[tid - 32] = be[tid - 32];
    for (int t = tid; t < KGB*DH; t += NT) {
        int k = t >> 6, n = t & 63;
        WtU[k * WTPAD + n] = tf32r(We[t]);
    }

    // dependent gather (src/dst should have landed by now)
    int gg  = eg / EPG;
    int zb  = gg * NPG;
    float x = XvG[gg * NPAIR + (dst - zb) * NPG + (src - zb)];
    __syncthreads();

    // ---- Pe rows: 2 threads/edge, 16 gaussians each (tf32, pitch 36) ----
    #pragma unroll
    for (int q = 0; q < 16; ++q) {
        int k = kh + q;
        float b = fmaf(x, sC1[k], sC2[k]);
        PeU[el * PEPAD + k] = tf32r(sNm[k] * fex2(-b * b));
    }
    __syncthreads();

    // ---- MMA: warp wid owns edges [wid*16, wid*16+16) ----
    {
        const int g4 = lane >> 2;
        const int t4 = lane & 3;
        const int m0 = wid * 16;
        const int r0 = (m0 + g4) * PEPAD;
        const int r1 = (m0 + g4 + 8) * PEPAD;
        uint32_t A[16];
        #pragma unroll
        for (int ks = 0; ks < 4; ++ks) {
            const int c0 = ks * 8 + t4;
            A[ks*4+0] = PeU[r0 + c0];
            A[ks*4+1] = PeU[r1 + c0];
            A[ks*4+2] = PeU[r0 + c0 + 4];
            A[ks*4+3] = PeU[r1 + c0 + 4];
        }
        __syncwarp();   // warp's Pe rows fully read -> safe to overlay staging

        // staging region = this warp's own Pe block (576 words = 8 rows x 72)
        float* stg = (float*)(PeU + m0 * PEPAD);
        float keep[16];

        // pass 1: compute all nt; stage rows g4 (c0,c1); keep rows g4+8
        #pragma unroll
        for (int nt = 0; nt < 8; ++nt) {
            float c[4] = {0.f, 0.f, 0.f, 0.f};
            #pragma unroll
            for (int ks = 0; ks < 4; ++ks) {
                uint32_t b0 = WtU[(ks*8 + t4)     * WTPAD + nt*8 + g4];
                uint32_t b1 = WtU[(ks*8 + t4 + 4) * WTPAD + nt*8 + g4];
                mma_tf32(c, A + ks*4, b0, b1);
            }
            *(float2*)(stg + g4 * STPAD + nt*8 + t4*2) = make_float2(c[0], c[1]);
            keep[nt*2]   = c[2];
            keep[nt*2+1] = c[3];
        }
        __syncwarp();

        const int colb = (lane & 7) * 4;
        const int rowb = lane >> 3;        // 0..3
        float4 b0 = *(const float4*)(sBe + colb);
        float4 b1 = *(const float4*)(sBe + colb + 32);

        // write rows m0 .. m0+7
        #pragma unroll
        for (int p = 0; p < 2; ++p) {
            const int r = rowb + 4*p;
            float4 v0 = *(const float4*)(stg + r * STPAD + colb);
            float4 v1 = *(const float4*)(stg + r * STPAD + colb + 32);
            v0.x += b0.x; v0.y += b0.y; v0.z += b0.z; v0.w += b0.w;
            v1.x += b1.x; v1.y += b1.y; v1.z += b1.z; v1.w += b1.w;
            float* o = out_edges + (size_t)(e0 + m0 + r) * DH;
            *(float4*)(o + colb)      = v0;
            *(float4*)(o + colb + 32) = v1;
        }
        __syncwarp();

        // pass 2: stage rows g4+8 from keep[]
        #pragma unroll
        for (int nt = 0; nt < 8; ++nt)
            *(float2*)(stg + g4 * STPAD + nt*8 + t4*2) =
                make_float2(keep[nt*2], keep[nt*2+1]);
        __syncwarp();

        // write rows m0+8 .. m0+15
        #pragma unroll
        for (int p = 0; p < 2; ++p) {
            const int r = rowb + 4*p;
            float4 v0 = *(const float4*)(stg + r * STPAD + colb);
            float4 v1 = *(const float4*)(stg + r * STPAD + colb + 32);
            v0.x += b0.x; v0.y += b0.y; v0.z += b0.z; v0.w += b0.w;
            v1.x += b1.x; v1.y += b1.y; v1.z += b1.z; v1.w += b1.w;
            float* o = out_edges + (size_t)(e0 + m0 + 8 + r) * DH;
            *(float4*)(o + colb)      = v0;
            *(float4*)(o + colb + 32) = v1;
        }
    }
}

extern "C" void kernel_launch(void* const* d_in, const int* in_sizes, int n_in,
                              void* d_out, int out_size)
{
    const int*   z    = (const int*)  d_in[0];
    const float* pos  = (const float*)d_in[1];
    const int*   ei   = (const int*)  d_in[3];
    const float* ae   = (const float*)d_in[4];
    const float* Wep  = (const float*)d_in[5];
    const float* bep  = (const float*)d_in[6];
    const float* mea  = (const float*)d_in[7];
    const float* stds = (const float*)d_in[8];
    const float* gmul = (const float*)d_in[9];
    const float* gbia = (const float*)d_in[10];
    const float* Wn   = (const float*)d_in[11];
    const float* bn   = (const float*)d_in[12];
    const float* We   = (const float*)d_in[13];
    const float* be   = (const float*)d_in[14];

    const int N = in_sizes[0];          // 49152
    const int E = in_sizes[3] / 2;      // 589824
    const int g = N / NPG;              // 2048

    float* out_nodes = (float*)d_out;
    float* out_edges = out_nodes + (size_t)N * DH;

    cudaFuncSetAttribute(node_kernel,
                         cudaFuncAttributeMaxDynamicSharedMemorySize, K1_BYTES);
    cudaFuncSetAttribute(edge_kernel,
                         cudaFuncAttributeMaxDynamicSharedMemorySize, K2_BYTES);

    node_kernel<<<g, NT, K1_BYTES>>>(z, pos, ae, Wep, bep, mea, stds,
                                     gmul, gbia, Wn, bn, out_nodes);
    edge_kernel<<<E / EPC, NT, K2_BYTES>>>(ei, We, be, mea, stds, out_edges, E);
}

// round 12
// speedup vs baseline: 1.9465x; 1.1410x over previous
#include <cuda_runtime.h>
#include <math.h>
#include <stdint.h>

#define NG    2048
#define NPG   24
#define EPG   288
#define KGB   32
#define EMB   32
#define DH    64
#define NT    256
#define NPAIR (NPG*NPG)          // 576
#define NATOM 10

typedef unsigned long long ull;

// global scratch: per-pair affine args (graph-major)
__device__ float XvG[NG * NPAIR];

// ---------------- packed fp32x2 helpers ----------------
__device__ __forceinline__ ull pk2(float lo, float hi) {
    ull r; asm("mov.b64 %0, {%1, %2};" : "=l"(r) : "f"(lo), "f"(hi)); return r;
}
__device__ __forceinline__ void upk2(ull v, float& lo, float& hi) {
    asm("mov.b64 {%0, %1}, %2;" : "=f"(lo), "=f"(hi) : "l"(v));
}
__device__ __forceinline__ ull ffma2(ull a, ull b, ull c) {
    ull d; asm("fma.rn.f32x2 %0, %1, %2, %3;" : "=l"(d) : "l"(a), "l"(b), "l"(c)); return d;
}
__device__ __forceinline__ float fex2(float x) {
    float r; asm("ex2.approx.f32 %0, %1;" : "=f"(r) : "f"(x)); return r;
}
__device__ __forceinline__ uint32_t tf32r(float x) {
    uint32_t r; asm("cvt.rna.tf32.f32 %0, %1;" : "=r"(r) : "f"(x)); return r;
}
__device__ __forceinline__ void mma_tf32(float* c, const uint32_t* a,
                                         uint32_t b0, uint32_t b1) {
    asm volatile("mma.sync.aligned.m16n8k8.row.col.f32.tf32.tf32.f32 "
        "{%0,%1,%2,%3}, {%4,%5,%6,%7}, {%8,%9}, {%0,%1,%2,%3};"
        : "+f"(c[0]), "+f"(c[1]), "+f"(c[2]), "+f"(c[3])
        : "r"(a[0]), "r"(a[1]), "r"(a[2]), "r"(a[3]), "r"(b0), "r"(b1));
}

// =====================================================================
// K1: node path (per-graph). smem layout (words)
// =====================================================================
#define N_XV    0                          // 576
#define N_S     (N_XV   + NPAIR)           // 768
#define N_GNF   (N_S    + NPG*KGB)         // 768
#define N_WEP   (N_GNF  + NPG*EMB)         // 1024 (ull packed [kk][m])
#define N_MUL   (N_WEP  + KGB*EMB)         // 100
#define N_BIAS  (N_MUL  + NATOM*NATOM)     // 100
#define N_C1    (N_BIAS + NATOM*NATOM)     // 32
#define N_C2    (N_C1   + KGB)             // 32
#define N_NORM  (N_C2   + KGB)             // 32
#define N_BEP   (N_NORM + KGB)             // 32
#define N_BN    (N_BEP  + EMB)             // 64
#define N_AE    (N_BN   + DH)              // 320
#define N_POS   (N_AE   + NATOM*EMB)       // 72
#define N_Z     (N_POS  + NPG*3)           // 24
#define K1_WORDS (N_Z + NPG)
#define K1_BYTES (K1_WORDS * 4)

extern __shared__ float sm[];

__global__ __launch_bounds__(NT, 4)
void node_kernel(const int* __restrict__ z,
                 const float* __restrict__ pos,
                 const float* __restrict__ atom_emb,
                 const float* __restrict__ Wep,
                 const float* __restrict__ bep,
                 const float* __restrict__ means,
                 const float* __restrict__ stds,
                 const float* __restrict__ gmul,
                 const float* __restrict__ gbias,
                 const float* __restrict__ Wn,
                 const float* __restrict__ bn,
                 float* __restrict__ out_nodes)
{
    const int g   = blockIdx.x;
    const int tid = threadIdx.x;
    const int zbase = g * NPG;

    float* Xv    = sm + N_XV;
    float* Ssum  = sm + N_S;
    float* Gnf   = sm + N_GNF;
    ull*   sWep2 = (ull*)(sm + N_WEP);
    float* sMul  = sm + N_MUL;
    float* sBias = sm + N_BIAS;
    float* sC1   = sm + N_C1;
    float* sC2   = sm + N_C2;
    float* sNorm = sm + N_NORM;
    float* sBep  = sm + N_BEP;
    float* sBn   = sm + N_BN;
    float* sAe   = sm + N_AE;
    float* sPos  = sm + N_POS;
    int*   sZ    = (int*)(sm + N_Z);

    // ---- tables ----
    if (tid < NPG) sZ[tid] = z[zbase + tid];
    for (int t = tid; t < NPG*3; t += NT) sPos[t] = pos[zbase*3 + t];
    for (int t = tid; t < (KGB/2)*EMB; t += NT) {
        int kk = t >> 5, m = t & 31;
        sWep2[kk * EMB + m] = pk2(Wep[(2*kk)*EMB + m], Wep[(2*kk+1)*EMB + m]);
    }
    for (int t = tid; t < NATOM*NATOM; t += NT) { sMul[t] = gmul[t]; sBias[t] = gbias[t]; }
    if (tid < KGB) {
        float s = fabsf(stds[tid]) + 1e-5f;
        float ik = 1.0f / s;
        float c1 = 0.8493218002880191f * ik;        // sqrt(0.5*log2(e))/s
        sC1[tid] = c1;
        sC2[tid] = -means[tid] * c1;
        sNorm[tid] = 0.3989422804014327f * ik;
    }
    if (tid >= KGB && tid < 2*KGB) sBep[tid - KGB] = bep[tid - KGB];
    if (tid >= 64 && tid < 128)  sBn[tid - 64] = bn[tid - 64];
    for (int t = tid; t < NATOM*EMB; t += NT) sAe[t] = atom_emb[t];
    __syncthreads();

    // ---- Xv: per-pair affine args, also stored to global scratch ----
    float* xvg = XvG + g * NPAIR;
    for (int p = tid; p < NPAIR; p += NT) {
        int i = p / NPG;
        int j = p - i * NPG;
        float dx = sPos[i*3+0] - sPos[j*3+0];
        float dy = sPos[i*3+1] - sPos[j*3+1];
        float dz = sPos[i*3+2] - sPos[j*3+2];
        float sq = dx*dx + dy*dy + dz*dz;
        float dist = (sq == 0.0f) ? 0.0f : sqrtf(sq);
        int et = sZ[i] * NATOM + sZ[j];
        float x = sMul[et] * dist + sBias[et];
        Xv[p] = x;
        xvg[p] = x;
    }
    __syncthreads();

    // ---- node sums S[i][k] = nk * sum_j exp2(-(c1*x+c2)^2) ----
    {
        const int k = tid & 31;
        const float c1k = sC1[k], c2k = sC2[k], nk = sNorm[k];
        for (int t = tid; t < NPG * KGB; t += NT) {
            int i = t >> 5;
            const float* xr = Xv + i * NPG;
            float s0 = 0.0f, s1 = 0.0f;
            #pragma unroll
            for (int j = 0; j < NPG; j += 2) {
                float b0 = fmaf(xr[j],   c1k, c2k);
                float b1 = fmaf(xr[j+1], c1k, c2k);
                s0 += fex2(-b0 * b0);
                s1 += fex2(-b1 * b1);
            }
            Ssum[t] = nk * (s0 + s1);
        }
    }
    __syncthreads();

    // ---- gnf = atom_emb[z_i] + S @ Wep + bep ----
    for (int t = tid; t < NPG * EMB; t += NT) {
        int i = t >> 5, m = t & 31;
        const ull* s2 = (const ull*)(Ssum + i * KGB);
        ull acc = 0;
        #pragma unroll
        for (int kk = 0; kk < KGB/2; ++kk)
            acc = ffma2(s2[kk], sWep2[kk * EMB + m], acc);
        float lo, hi; upk2(acc, lo, hi);
        Gnf[t] = sAe[sZ[i] * EMB + m] + sBep[m] + lo + hi;
    }
    __syncthreads();

    // ---- node_feat = gnf @ W_nodes + b_nodes ----
    {
        const int d = tid & (DH - 1);
        const int isub = tid >> 6;
        ull w[EMB/2];
        #pragma unroll
        for (int mm = 0; mm < EMB/2; ++mm)
            w[mm] = pk2(Wn[(2*mm)*DH + d], Wn[(2*mm+1)*DH + d]);
        const float bd = sBn[d];
        for (int i = isub; i < NPG; i += NT/DH) {
            const ull* g2 = (const ull*)(Gnf + i * EMB);
            ull a0 = 0, a1 = 0;
            #pragma unroll
            for (int mm = 0; mm < EMB/2; mm += 2) {
                a0 = ffma2(g2[mm],   w[mm],   a0);
                a1 = ffma2(g2[mm+1], w[mm+1], a1);
            }
            float l0, h0, l1, h1; upk2(a0, l0, h0); upk2(a1, l1, h1);
            out_nodes[(size_t)(zbase + i) * DH + d] = bd + l0 + h0 + l1 + h1;
        }
    }
}

// =====================================================================
// K2: edge path. 128 edges/CTA. A-fragments computed directly in the
// owning MMA thread (no Pe tile, no transpose smem round-trip).
// =====================================================================
#define EPC    128                         // edges per CTA
#define WTPAD  72
#define STPAD  72                          // staging pitch (8 rows/warp)

#define E_WT    0                          // 2304
#define E_STG   (E_WT + KGB*WTPAD)         // 8 warps * 8*72 = 4608
#define E_C1    (E_STG + 8*8*STPAD)        // 32
#define E_C2    (E_C1 + KGB)               // 32
#define E_NORM  (E_C2 + KGB)               // 32
#define E_BE    (E_NORM + KGB)             // 64
#define K2_WORDS (E_BE + DH)               // 7072 words = 28288 B
#define K2_BYTES (K2_WORDS * 4)

__global__ __launch_bounds__(NT, 4)
void edge_kernel(const int* __restrict__ edge_index,
                 const float* __restrict__ We,
                 const float* __restrict__ be,
                 const float* __restrict__ means,
                 const float* __restrict__ stds,
                 float* __restrict__ out_edges,
                 int E)
{
    const int tid  = threadIdx.x;
    const int wid  = tid >> 5;
    const int lane = tid & 31;
    const int e0   = blockIdx.x * EPC;

    uint32_t* WtU = (uint32_t*)(sm + E_WT);
    float*    sC1 = sm + E_C1;
    float*    sC2 = sm + E_C2;
    float*    sNm = sm + E_NORM;
    float*    sBe = sm + E_BE;

    const int g4 = lane >> 2;          // 0..7  (A-fragment row group)
    const int t4 = lane & 3;           // 0..3  (A-fragment col group)
    const int m0 = wid * 16;

    // ---- issue the edge gather chain FIRST (overlaps table setup) ----
    const int el0 = e0 + m0 + g4;
    const int el1 = el0 + 8;
    int s0 = edge_index[el0];
    int s1 = edge_index[el1];
    int d0 = edge_index[E + el0];
    int d1 = edge_index[E + el1];

    // ---- tables (overlap with gather latency) ----
    if (tid < KGB) {
        float s = fabsf(stds[tid]) + 1e-5f;
        float ik = 1.0f / s;
        float c1 = 0.8493218002880191f * ik;
        sC1[tid] = c1;
        sC2[tid] = -means[tid] * c1;
        sNm[tid] = 0.3989422804014327f * ik;
    }
    if (tid >= 32 && tid < 96) sBe[tid - 32] = be[tid - 32];
    for (int t = tid; t < KGB*DH; t += NT) {
        int k = t >> 6, n = t & 63;
        WtU[k * WTPAD + n] = tf32r(We[t]);
    }

    // dependent XvG gathers (idx LDGs should have landed)
    {
        int gg0 = el0 / EPG, zb0 = gg0 * NPG;
        int gg1 = el1 / EPG, zb1 = gg1 * NPG;
        s0 = gg0 * NPAIR + (d0 - zb0) * NPG + (s0 - zb0);
        s1 = gg1 * NPAIR + (d1 - zb1) * NPG + (s1 - zb1);
    }
    float x0 = XvG[s0];
    float x1 = XvG[s1];
    __syncthreads();

    // ---- A fragments: computed in place (rows m0+g4, m0+g4+8; cols k≡t4 mod 4)
    uint32_t A[16];
    #pragma unroll
    for (int ks = 0; ks < 4; ++ks) {
        #pragma unroll
        for (int h = 0; h < 2; ++h) {
            int k = ks*8 + t4 + h*4;
            float c1 = sC1[k], c2 = sC2[k], nm = sNm[k];
            float b0 = fmaf(x0, c1, c2);
            float b1 = fmaf(x1, c1, c2);
            A[ks*4 + h*2 + 0] = tf32r(nm * fex2(-b0 * b0));
            A[ks*4 + h*2 + 1] = tf32r(nm * fex2(-b1 * b1));
        }
    }

    // ---- MMA + 2-pass staged epilogue (per-warp staging, no CTA barrier) ----
    {
        float* stg = sm + E_STG + wid * 8 * STPAD;
        float keep[16];

        // pass 1: compute all nt; stage rows g4 (c0,c1); keep rows g4+8
        #pragma unroll
        for (int nt = 0; nt < 8; ++nt) {
            float c[4] = {0.f, 0.f, 0.f, 0.f};
            #pragma unroll
            for (int ks = 0; ks < 4; ++ks) {
                uint32_t b0 = WtU[(ks*8 + t4)     * WTPAD + nt*8 + g4];
                uint32_t b1 = WtU[(ks*8 + t4 + 4) * WTPAD + nt*8 + g4];
                mma_tf32(c, A + ks*4, b0, b1);
            }
            *(float2*)(stg + g4 * STPAD + nt*8 + t4*2) = make_float2(c[0], c[1]);
            keep[nt*2]   = c[2];
            keep[nt*2+1] = c[3];
        }
        __syncwarp();

        const int colb = (lane & 7) * 4;
        const int rowb = lane >> 3;        // 0..3
        float4 b0 = *(const float4*)(sBe + colb);
        float4 b1 = *(const float4*)(sBe + colb + 32);

        // write rows m0 .. m0+7
        #pragma unroll
        for (int p = 0; p < 2; ++p) {
            const int r = rowb + 4*p;
            float4 v0 = *(const float4*)(stg + r * STPAD + colb);
            float4 v1 = *(const float4*)(stg + r * STPAD + colb + 32);
            v0.x += b0.x; v0.y += b0.y; v0.z += b0.z; v0.w += b0.w;
            v1.x += b1.x; v1.y += b1.y; v1.z += b1.z; v1.w += b1.w;
            float* o = out_edges + (size_t)(e0 + m0 + r) * DH;
            *(float4*)(o + colb)      = v0;
            *(float4*)(o + colb + 32) = v1;
        }
        __syncwarp();

        // pass 2: stage rows g4+8 from keep[]
        #pragma unroll
        for (int nt = 0; nt < 8; ++nt)
            *(float2*)(stg + g4 * STPAD + nt*8 + t4*2) =
                make_float2(keep[nt*2], keep[nt*2+1]);
        __syncwarp();

        // write rows m0+8 .. m0+15
        #pragma unroll
        for (int p = 0; p < 2; ++p) {
            const int r = rowb + 4*p;
            float4 v0 = *(const float4*)(stg + r * STPAD + colb);
            float4 v1 = *(const float4*)(stg + r * STPAD + colb + 32);
            v0.x += b0.x; v0.y += b0.y; v0.z += b0.z; v0.w += b0.w;
            v1.x += b1.x; v1.y += b1.y; v1.z += b1.z; v1.w += b1.w;
            float* o = out_edges + (size_t)(e0 + m0 + 8 + r) * DH;
            *(float4*)(o + colb)      = v0;
            *(float4*)(o + colb + 32) = v1;
        }
    }
}

extern "C" void kernel_launch(void* const* d_in, const int* in_sizes, int n_in,
                              void* d_out, int out_size)
{
    const int*   z    = (const int*)  d_in[0];
    const float* pos  = (const float*)d_in[1];
    const int*   ei   = (const int*)  d_in[3];
    const float* ae   = (const float*)d_in[4];
    const float* Wep  = (const float*)d_in[5];
    const float* bep  = (const float*)d_in[6];
    const float* mea  = (const float*)d_in[7];
    const float* stds = (const float*)d_in[8];
    const float* gmul = (const float*)d_in[9];
    const float* gbia = (const float*)d_in[10];
    const float* Wn   = (const float*)d_in[11];
    const float* bn   = (const float*)d_in[12];
    const float* We   = (const float*)d_in[13];
    const float* be   = (const float*)d_in[14];

    const int N = in_sizes[0];          // 49152
    const int E = in_sizes[3] / 2;      // 589824
    const int g = N / NPG;              // 2048

    float* out_nodes = (float*)d_out;
    float* out_edges = out_nodes + (size_t)N * DH;

    cudaFuncSetAttribute(node_kernel,
                         cudaFuncAttributeMaxDynamicSharedMemorySize, K1_BYTES);
    cudaFuncSetAttribute(edge_kernel,
                         cudaFuncAttributeMaxDynamicSharedMemorySize, K2_BYTES);

    node_kernel<<<g, NT, K1_BYTES>>>(z, pos, ae, Wep, bep, mea, stds,
                                     gmul, gbia, Wn, bn, out_nodes);
    edge_kernel<<<E / EPC, NT, K2_BYTES>>>(ei, We, be, mea, stds, out_edges, E);
}